// round 7
// baseline (speedup 1.0000x reference)
#include <cuda_runtime.h>
#include <cstdint>
#include <float.h>

#define BATCH 16
#define HH 96
#define WW 320
#define HWSZ (HH*WW)      // 30720
#define KTOP 100
#define NMAPS 12          // 3 hm + 9 hm_hp
#define THRESH 0.1f

#define T1 352            // 11 warps: warp w covers columns [30w-1 .. 30w+30]
#define NBANDS 4
#define BROWS 24          // rows per band
#define SURV_CAP 2048
#define NHIST 8192
#define PF 4              // prefetch depth (rows in flight)

typedef unsigned long long u64;

// ---------------- scratch (no cudaMalloc allowed) ----------------
__device__ u64   g_keys_band[BATCH*NMAPS*NBANDS*KTOP];   // per-band sorted top-100
__device__ float g_scores[BATCH*NMAPS*KTOP];             // per-map sorted top-100
__device__ int   g_inds  [BATCH*NMAPS*KTOP];
__device__ float g_fscore[BATCH*KTOP];
__device__ int   g_find  [BATCH*KTOP];
__device__ int   g_fcls  [BATCH*KTOP];

__device__ __forceinline__ float sigmoidf_(float x){ return 1.0f/(1.0f + expf(-x)); }

__device__ __forceinline__ u64 packkey(float v, unsigned idx){
    return ((u64)__float_as_uint(v) << 32) | (unsigned)(~idx);
}

// sortable uint from float bits (monotone, handles negatives)
__device__ __forceinline__ unsigned fsort(float f){
    unsigned u = __float_as_uint(f);
    return u ^ (((unsigned)((int)u >> 31)) | 0x80000000u);
}
__device__ __forceinline__ float funsort(unsigned us){
    unsigned u = (us & 0x80000000u) ? (us ^ 0x80000000u) : ~us;
    return __uint_as_float(u);
}

// =====================================================================
// Kernel 1: per-(map,band) streaming RAW 3x3 NMS + band top-100
// =====================================================================
__global__ __launch_bounds__(T1, 4)
void topk_band_kernel(const float* __restrict__ hm, const float* __restrict__ hm_hp){
    int m = blockIdx.x / NBANDS;     // map id: b*NMAPS + map
    int q = blockIdx.x % NBANDS;     // band id
    int b   = m / NMAPS;
    int map = m - b*NMAPS;
    const float* src = (map < 3) ? (hm    + (size_t)(b*3 +  map     )*HWSZ)
                                 : (hm_hp + (size_t)(b*9 + (map - 3))*HWSZ);

    extern __shared__ char smraw[];
    u64* s_surv = (u64*)smraw;                        // 2048*8 = 16384
    int* s_hist = (int*)(smraw + 16384);              // 8192*4 = 32768
    u64* s_key  = (u64*)(smraw + 49152);              // 512*8  = 4096
    int* s_part = (int*)(smraw + 53248);              // 256*4  = 1024
    __shared__ int s_cnt, s_ccnt, s_thresh;

    int tid  = threadIdx.x;
    int warp = tid >> 5;
    int lane = tid & 31;
    int x    = 30*warp + lane - 1;                    // -1 .. 330
    bool inx = (x >= 0) && (x < WW);
    bool owner = (lane >= 1) && (lane <= 30) && (x < WW);
    int ybase = q*BROWS - 1;                          // first (halo) row

    for (int i = tid; i < NHIST; i += T1) s_hist[i] = 0;
    if (tid == 0){ s_cnt = 0; s_ccnt = 0; s_thresh = 0; }

    const float NEG = -FLT_MAX;
    float pf[PF];
    #pragma unroll
    for (int i = 0; i < PF; i++){
        int r = ybase + i;
        pf[i] = (inx && r >= 0 && r < HH) ? __ldg(src + r*WW + x) : NEG;
    }

    float h1 = NEG, h0 = NEG, s_prev = NEG;

    __syncthreads();   // hist ready before any emit

    #pragma unroll 2
    for (int yy = 0; yy < BROWS + 2; yy++){
        int r = ybase + yy;
        float s = pf[yy % PF];
        {
            int rn = r + PF;
            if (inx && yy + PF < BROWS + 2 && rn >= 0 && rn < HH)
                pf[yy % PF] = __ldg(src + rn*WW + x);
        }
        if (!inx || r < 0 || r >= HH) s = NEG;
        float l  = __shfl_up_sync(0xffffffffu, s, 1);
        float rr = __shfl_down_sync(0xffffffffu, s, 1);
        float h  = fmaxf(fmaxf(l, rr), s);

        if (yy >= 2 && owner){           // emit row r-1 (strictly inside band)
            float vmax = fmaxf(fmaxf(h1, h0), h);
            bool surv = (vmax == s_prev);
            if (!surv && (vmax - s_prev) < 1e-4f){
                // borderline: reference compares sigmoids, may round equal
                surv = (__float_as_uint(sigmoidf_(vmax)) ==
                        __float_as_uint(sigmoidf_(s_prev)));
            }
            if (surv){
                unsigned us = fsort(s_prev);
                atomicAdd(&s_hist[us >> 19], 1);
                int pos = atomicAdd(&s_cnt, 1);
                if (pos < SURV_CAP)
                    s_surv[pos] = ((u64)us << 32) | (unsigned)(~((r-1)*WW + x));
            }
        }
        h1 = h0; h0 = h; s_prev = s;
    }
    __syncthreads();

    // ---- parallel radix-select: chunk partials + prefix scan ----
    int psum = 0;
    if (tid < 256){
        int hi = NHIST - 32*tid;     // covers [hi-32, hi), chunks from top
        #pragma unroll
        for (int i = hi-32; i < hi; i++) psum += s_hist[i];
        s_part[tid] = psum;
    }
    __syncthreads();
    #pragma unroll
    for (int off = 1; off < 256; off <<= 1){
        int v = 0;
        if (tid < 256 && tid >= off) v = s_part[tid - off];
        __syncthreads();
        if (tid < 256) s_part[tid] += v;
        __syncthreads();
    }
    if (tid < 256){
        int incl = s_part[tid];
        int excl = incl - psum;
        if (excl < KTOP && incl >= KTOP){   // exactly one chunk crosses
            int hi2 = NHIST - 32*tid;
            int acc = excl, thr = 0;
            for (int i = hi2-1; i >= hi2-32; i--){
                acc += s_hist[i];
                if (acc >= KTOP){ thr = i; break; }
            }
            s_thresh = (thr > 0) ? thr - 1 : 0;  // one-bucket margin: sigmoid ties
        }
    }
    __syncthreads();

    // collect candidates (raw-bits >= threshold), substituting sigmoid keys
    unsigned ut = (unsigned)s_thresh << 19;
    int ns = min(s_cnt, SURV_CAP);
    for (int i = tid; i < ns; i += T1){
        u64 key = s_surv[i];
        unsigned us = (unsigned)(key >> 32);
        if (us >= ut){
            int pos = atomicAdd(&s_ccnt, 1);
            if (pos < 512){
                float sig = sigmoidf_(funsort(us));
                s_key[pos] = ((u64)__float_as_uint(sig) << 32) | (unsigned)key;
            }
        }
    }
    __syncthreads();
    int nc = min(s_ccnt, 512);
    int SS = (nc <= 256) ? 256 : 512;     // dynamic sort size
    for (int i = tid; i < SS; i += T1) if (i >= nc) s_key[i] = 0ULL;
    __syncthreads();

    // bitonic sort descending: (sigmoid desc, index asc)
    for (int kk = 2; kk <= SS; kk <<= 1){
        for (int jj = kk >> 1; jj > 0; jj >>= 1){
            for (int i = tid; i < SS; i += T1){
                int ixj = i ^ jj;
                if (ixj > i){
                    u64 a = s_key[i], c2 = s_key[ixj];
                    bool up = ((i & kk) == 0);
                    if (up ? (a < c2) : (a > c2)){ s_key[i] = c2; s_key[ixj] = a; }
                }
            }
            __syncthreads();
        }
    }

    if (tid < KTOP)
        g_keys_band[(size_t)blockIdx.x*KTOP + tid] = s_key[tid];
}

// =====================================================================
// Kernel 2: per-map merge of 4 band top-100s -> sorted map top-100
// =====================================================================
__global__ __launch_bounds__(512)
void merge_map_kernel(){
    __shared__ u64 sk[512];
    int m = blockIdx.x;          // 0..191
    int tid = threadIdx.x;

    sk[tid] = (tid < 400)
        ? g_keys_band[((size_t)m*NBANDS + tid/100)*KTOP + tid%100]
        : 0ULL;
    __syncthreads();
    for (int kk = 2; kk <= 512; kk <<= 1){
        for (int jj = kk >> 1; jj > 0; jj >>= 1){
            int i = tid, ixj = tid ^ jj;
            if (ixj > i){
                u64 a = sk[i], c2 = sk[ixj];
                bool up = ((i & kk) == 0);
                if (up ? (a < c2) : (a > c2)){ sk[i] = c2; sk[ixj] = a; }
            }
            __syncthreads();
        }
    }
    if (tid < KTOP){
        u64 key = sk[tid];
        g_scores[m*KTOP + tid] = __uint_as_float((unsigned)(key >> 32));
        g_inds  [m*KTOP + tid] = (int)(~(unsigned)key);
    }
}

// =====================================================================
// Kernel 3: per-batch top-100 over 3x100 hm-channel candidates
// =====================================================================
__global__ __launch_bounds__(512)
void merge_batch_kernel(){
    __shared__ u64 s_key[512];
    int b = blockIdx.x, tid = threadIdx.x;

    if (tid < 300){
        int c = tid / 100, k = tid - c*100;
        float v = g_scores[(b*NMAPS + c)*KTOP + k];
        s_key[tid] = packkey(v, (unsigned)tid);
    } else s_key[tid] = 0ULL;
    __syncthreads();
    for (int kk = 2; kk <= 512; kk <<= 1){
        for (int jj = kk >> 1; jj > 0; jj >>= 1){
            int i = tid, ixj = tid ^ jj;
            if (ixj > i){
                u64 a = s_key[i], c2 = s_key[ixj];
                bool up = ((i & kk) == 0);
                if (up ? (a < c2) : (a > c2)){ s_key[i] = c2; s_key[ixj] = a; }
            }
            __syncthreads();
        }
    }
    if (tid < KTOP){
        u64 key = s_key[tid];
        unsigned flat = ~(unsigned)key;
        int cls = flat / 100, kk2 = flat - cls*100;
        g_fscore[b*KTOP + tid] = __uint_as_float((unsigned)(key >> 32));
        g_fcls  [b*KTOP + tid] = cls;
        g_find  [b*KTOP + tid] = g_inds[(b*NMAPS + cls)*KTOP + kk2];
    }
}

// =====================================================================
// Kernel 4: 160 CTAs. jobs 0-8 = joint matching; job 9 = scalar gathers
// =====================================================================
__global__ __launch_bounds__(128)
void decode_kernel(const float* __restrict__ wh,  const float* __restrict__ hps,
                   const float* __restrict__ dim, const float* __restrict__ rot,
                   const float* __restrict__ prob,const float* __restrict__ reg,
                   const float* __restrict__ hp_offset, float* __restrict__ out){
    int job = blockIdx.x;
    int b   = blockIdx.y;
    int tid = threadIdx.x;

    if (job == 9){
        if (tid < KTOP){
            int k = tid;
            int ind = g_find[b*KTOP + k];
            float x0 = (float)(ind % WW);
            float y0 = (float)(ind / WW);
            float rx = reg[((size_t)b*2 + 0)*HWSZ + ind];
            float ry = reg[((size_t)b*2 + 1)*HWSZ + ind];
            float xs = x0 + rx, ys = y0 + ry;
            float w0 = wh[((size_t)b*2 + 0)*HWSZ + ind];
            float w1 = wh[((size_t)b*2 + 1)*HWSZ + ind];
            float* det = out + ((size_t)b*KTOP + k)*45;
            det[0] = (xs - w0*0.5f)*4.0f;
            det[1] = (ys - w1*0.5f)*4.0f;
            det[2] = (xs + w0*0.5f)*4.0f;
            det[3] = (ys + w1*0.5f)*4.0f;
            det[4] = g_fscore[b*KTOP + k];
            det[23] = dim[((size_t)b*3 + 0)*HWSZ + ind];
            det[24] = dim[((size_t)b*3 + 1)*HWSZ + ind];
            det[25] = dim[((size_t)b*3 + 2)*HWSZ + ind];
            #pragma unroll
            for (int c = 0; c < 8; c++)
                det[35 + c] = rot[((size_t)b*8 + c)*HWSZ + ind];
            det[43] = prob[(size_t)b*HWSZ + ind];
            det[44] = (float)g_fcls[b*KTOP + k];
        }
        return;
    }

    int j = job;
    __shared__ float hmx[100], hmy[100], hmsc[100];
    __shared__ float bl[100], bt[100], br[100], bbm[100];
    __shared__ float kx[100], ky[100];

    if (tid < KTOP){
        int k = tid;
        int base = (b*NMAPS + 3 + j)*KTOP + k;
        int ind  = g_inds[base];
        float sc = g_scores[base];
        float ox = hp_offset[((size_t)b*2 + 0)*HWSZ + ind];
        float oy = hp_offset[((size_t)b*2 + 1)*HWSZ + ind];
        float xq = (float)(ind % WW) + ox;
        float yq = (float)(ind / WW) + oy;
        bool valid = sc > THRESH;
        hmsc[k] = valid ? sc : -1.0f;
        hmx [k] = valid ? xq : -10000.0f;
        hmy [k] = valid ? yq : -10000.0f;

        int ind2 = g_find[b*KTOP + k];
        float x0 = (float)(ind2 % WW);
        float y0 = (float)(ind2 / WW);
        float rx = reg[((size_t)b*2 + 0)*HWSZ + ind2];
        float ry = reg[((size_t)b*2 + 1)*HWSZ + ind2];
        float xs = x0 + rx, ys = y0 + ry;
        float w0 = wh[((size_t)b*2 + 0)*HWSZ + ind2];
        float w1 = wh[((size_t)b*2 + 1)*HWSZ + ind2];
        bl[k] = xs - w0*0.5f; bt[k]  = ys - w1*0.5f;
        br[k] = xs + w0*0.5f; bbm[k] = ys + w1*0.5f;
        kx[k] = hps[((size_t)b*18 + 2*j    )*HWSZ + ind2] + x0;
        ky[k] = hps[((size_t)b*18 + 2*j + 1)*HWSZ + ind2] + y0;
    }
    __syncthreads();

    if (tid < KTOP){
        int k = tid;
        float px = kx[k], py = ky[k];
        float best = FLT_MAX; int bm = 0;
        #pragma unroll 4
        for (int mm = 0; mm < 100; mm++){
            float dx = px - hmx[mm];
            float dy = py - hmy[mm];
            float d  = sqrtf(dx*dx + dy*dy);
            if (d < best){ best = d; bm = mm; }
        }
        float hs = hmsc[bm], hx = hmx[bm], hy = hmy[bm];
        float l = bl[k], tt = bt[k], r = br[k], bo = bbm[k];
        bool invalid = (hx < l) || (hx > r) || (hy < tt) || (hy > bo) ||
                       (hs < THRESH) ||
                       (best > fmaxf(bo - tt, r - l)*0.3f);
        float fx = invalid ? px : hx;
        float fy = invalid ? py : hy;
        float* det = out + ((size_t)b*KTOP + k)*45;
        det[5 + 2*j] = fx*4.0f;
        det[6 + 2*j] = fy*4.0f;
        det[26 + j]  = hs;
    }
}

// =====================================================================
extern "C" void kernel_launch(void* const* d_in, const int* in_sizes, int n_in,
                              void* d_out, int out_size){
    const float* hm        = (const float*)d_in[0];
    const float* wh        = (const float*)d_in[1];
    const float* hps       = (const float*)d_in[2];
    const float* dim       = (const float*)d_in[3];
    const float* rot       = (const float*)d_in[4];
    const float* prob      = (const float*)d_in[5];
    const float* reg       = (const float*)d_in[6];
    const float* hm_hp     = (const float*)d_in[7];
    const float* hp_offset = (const float*)d_in[8];
    float* out = (float*)d_out;

    const int SMEM1 = 16384 + 32768 + 4096 + 1024;   // 54272 B
    cudaFuncSetAttribute(topk_band_kernel,
                         cudaFuncAttributeMaxDynamicSharedMemorySize, SMEM1);

    topk_band_kernel<<<BATCH*NMAPS*NBANDS, T1, SMEM1>>>(hm, hm_hp);
    merge_map_kernel<<<BATCH*NMAPS, 512>>>();
    merge_batch_kernel<<<BATCH, 512>>>();
    decode_kernel<<<dim3(10, BATCH), 128>>>(wh, hps, dim, rot, prob, reg, hp_offset, out);
}

// round 9
// speedup vs baseline: 1.4947x; 1.4947x over previous
#include <cuda_runtime.h>
#include <cstdint>
#include <float.h>

#define BATCH 16
#define HH 96
#define WW 320
#define HWSZ (HH*WW)      // 30720
#define KTOP 100
#define NMAPS 12          // 3 hm + 9 hm_hp
#define THRESH 0.1f

#define T1 704            // 22 warps: 2 row-bands x 11 column-warps
#define NW 22
#define WSURV 256         // survivor slots per warp (power of 2)
#define NHIST 8192

typedef unsigned long long u64;

// ---------------- scratch (no cudaMalloc allowed) ----------------
__device__ float g_scores[BATCH*NMAPS*KTOP];
__device__ int   g_inds  [BATCH*NMAPS*KTOP];
__device__ float g_fscore[BATCH*KTOP];
__device__ int   g_find  [BATCH*KTOP];
__device__ int   g_fcls  [BATCH*KTOP];

__device__ __forceinline__ float sigmoidf_(float x){ return 1.0f/(1.0f + expf(-x)); }

__device__ __forceinline__ u64 packkey(float v, unsigned idx){
    return ((u64)__float_as_uint(v) << 32) | (unsigned)(~idx);
}

// sortable uint from float bits (monotone, handles negatives)
__device__ __forceinline__ unsigned fsort(float f){
    unsigned u = __float_as_uint(f);
    return u ^ (((unsigned)((int)u >> 31)) | 0x80000000u);
}
__device__ __forceinline__ float funsort(unsigned us){
    unsigned u = (us & 0x80000000u) ? (us ^ 0x80000000u) : ~us;
    return __uint_as_float(u);
}

// =====================================================================
// Kernel 1: per-(batch,channel) streaming RAW 3x3 NMS + top-100
//   2 row-bands x 11 col-warps; scalar 4-stage prefetch (no spills);
//   per-warp survivor buffers (no same-address atomics);
//   sigmoid only on ~O(100) candidates; parallel select + bitonic
// =====================================================================
__global__ __launch_bounds__(T1, 2)
void topk_map_kernel(const float* __restrict__ hm, const float* __restrict__ hm_hp){
    int blk = blockIdx.x;            // b*NMAPS + map
    int b   = blk / NMAPS;
    int map = blk - b*NMAPS;
    const float* src = (map < 3) ? (hm    + (size_t)(b*3 +  map     )*HWSZ)
                                 : (hm_hp + (size_t)(b*9 + (map - 3))*HWSZ);

    extern __shared__ char smraw[];
    u64* s_surv = (u64*)smraw;                        // NW*WSURV*8 = 45056
    int* s_hist = (int*)(smraw + 45056);              // 8192*4 = 32768
    u64* s_key  = (u64*)(smraw + 77824);              // 512*8  = 4096
    int* s_part = (int*)(smraw + 81920);              // 256*4  = 1024
    int* s_wcnt = (int*)(smraw + 82944);              // 22*4   = 88
    __shared__ int s_ccnt, s_thresh;

    int tid  = threadIdx.x;
    int warp = tid >> 5;
    int lane = tid & 31;
    int g    = warp / 11;            // row band 0/1
    int w    = warp - 11*g;          // column warp
    int x    = 30*w + lane - 1;      // -1 .. 330
    bool inx = (x >= 0) && (x < WW);
    bool owner = (lane >= 1) && (lane <= 30) && (x < WW);
    int ybase = g*48 - 1;            // first (halo) row

    {   // fast hist zero (uint4)
        uint4* h4 = (uint4*)s_hist;
        for (int i = tid; i < NHIST/4; i += T1) h4[i] = make_uint4(0,0,0,0);
    }
    if (tid < NW) s_wcnt[tid] = 0;
    if (tid == 0){ s_ccnt = 0; s_thresh = 0; }

    const float NEG = -FLT_MAX;
    const float* colp = src + x;     // column base (valid only if inx)
    int* mycnt = &s_wcnt[warp];
    u64* mybuf = &s_surv[warp << 8]; // warp region, WSURV=256

    // prime 4-stage scalar pipeline with rows ybase..ybase+3
    float pf0 = (inx && ybase+0 >= 0) ? __ldg(colp + (ybase+0)*WW) : NEG;
    float pf1 =  inx                  ? __ldg(colp + (ybase+1)*WW) : NEG;
    float pf2 =  inx                  ? __ldg(colp + (ybase+2)*WW) : NEG;
    float pf3 =  inx                  ? __ldg(colp + (ybase+3)*WW) : NEG;

    float h1 = NEG, h0 = NEG, s_prev = NEG;

    __syncthreads();   // hist/wcnt ready before any emit

#define STEP(PFREG, YY_)                                                     \
    {                                                                        \
        int yy = (YY_);                                                      \
        float s = (yy < 50) ? (PFREG) : NEG;                                 \
        int rn = ybase + yy + 4;                                             \
        if (inx && yy + 4 < 50 && rn < HH) PFREG = __ldg(colp + rn*WW);      \
        float lv = __shfl_up_sync(0xffffffffu, s, 1);                        \
        float rv = __shfl_down_sync(0xffffffffu, s, 1);                      \
        float h  = fmaxf(fmaxf(lv, rv), s);                                  \
        if (yy >= 2 && yy < 50 && owner){   /* emit rows ybase+1..ybase+48 */ \
            float vmax = fmaxf(fmaxf(h1, h0), h);                            \
            bool surv = (vmax == s_prev);                                    \
            if (!surv && (vmax - s_prev) < 1e-4f){                           \
                surv = (__float_as_uint(sigmoidf_(vmax)) ==                  \
                        __float_as_uint(sigmoidf_(s_prev)));                 \
            }                                                                \
            if (surv){                                                       \
                unsigned us = fsort(s_prev);                                 \
                atomicAdd(&s_hist[us >> 19], 1);                             \
                int pos = atomicAdd(mycnt, 1);                               \
                if (pos < WSURV)                                             \
                    mybuf[pos] = ((u64)us << 32) |                           \
                                 (unsigned)(~((ybase + yy - 1)*WW + x));     \
            }                                                                \
        }                                                                    \
        h1 = h0; h0 = h; s_prev = s;                                         \
    }

    // rows ybase..ybase+49 streamed; emission happens at yy = 2..49
    for (int yb = 0; yb < 52; yb += 4){
        STEP(pf0, yb+0)
        STEP(pf1, yb+1)
        STEP(pf2, yb+2)
        STEP(pf3, yb+3)
    }
#undef STEP
    __syncthreads();

    // ---- parallel radix-select: chunk partials + prefix scan ----
    int psum = 0;
    if (tid < 256){
        int hi = NHIST - 32*tid;     // covers [hi-32, hi), chunks from top
        #pragma unroll
        for (int i = hi-32; i < hi; i++) psum += s_hist[i];
        s_part[tid] = psum;
    }
    __syncthreads();
    #pragma unroll
    for (int off = 1; off < 256; off <<= 1){
        int v = 0;
        if (tid < 256 && tid >= off) v = s_part[tid - off];
        __syncthreads();
        if (tid < 256) s_part[tid] += v;
        __syncthreads();
    }
    if (tid < 256){
        int incl = s_part[tid];
        int excl = incl - psum;
        if (excl < KTOP && incl >= KTOP){   // exactly one chunk crosses
            int hi2 = NHIST - 32*tid;
            int acc = excl, thr = 0;
            for (int i = hi2-1; i >= hi2-32; i--){
                acc += s_hist[i];
                if (acc >= KTOP){ thr = i; break; }
            }
            s_thresh = (thr > 0) ? thr - 1 : 0;  // one-bucket margin: sigmoid ties
        }
    }
    __syncthreads();

    // collect candidates (raw-bits >= threshold), substituting sigmoid keys
    unsigned ut = (unsigned)s_thresh << 19;
    for (int i = tid; i < NW*WSURV; i += T1){
        int wi = i >> 8, o = i & (WSURV-1);
        if (o < s_wcnt[wi]){
            u64 key = s_surv[i];
            unsigned us = (unsigned)(key >> 32);
            if (us >= ut){
                int pos = atomicAdd(&s_ccnt, 1);
                if (pos < 512){
                    float sig = sigmoidf_(funsort(us));
                    s_key[pos] = ((u64)__float_as_uint(sig) << 32) | (unsigned)key;
                }
            }
        }
    }
    __syncthreads();
    int nc = min(s_ccnt, 512);
    int SS = (nc <= 256) ? 256 : 512;     // dynamic sort size
    for (int i = tid; i < SS; i += T1) if (i >= nc) s_key[i] = 0ULL;
    __syncthreads();

    // bitonic sort descending: (sigmoid desc, index asc)
    for (int kk = 2; kk <= SS; kk <<= 1){
        for (int jj = kk >> 1; jj > 0; jj >>= 1){
            for (int i = tid; i < SS; i += T1){
                int ixj = i ^ jj;
                if (ixj > i){
                    u64 a = s_key[i], c2 = s_key[ixj];
                    bool up = ((i & kk) == 0);
                    if (up ? (a < c2) : (a > c2)){ s_key[i] = c2; s_key[ixj] = a; }
                }
            }
            __syncthreads();
        }
    }

    if (tid < KTOP){
        u64 key = s_key[tid];
        g_scores[blk*KTOP + tid] = __uint_as_float((unsigned)(key >> 32));
        g_inds  [blk*KTOP + tid] = (int)(~(unsigned)key);
    }
}

// =====================================================================
// Kernel 2: per-batch top-100 over 3x100 hm-channel candidates
// =====================================================================
__global__ __launch_bounds__(512)
void merge_batch_kernel(){
    __shared__ u64 s_key[512];
    int b = blockIdx.x, tid = threadIdx.x;

    if (tid < 300){
        int c = tid / 100, k = tid - c*100;
        float v = g_scores[(b*NMAPS + c)*KTOP + k];
        s_key[tid] = packkey(v, (unsigned)tid);
    } else s_key[tid] = 0ULL;
    __syncthreads();
    for (int kk = 2; kk <= 512; kk <<= 1){
        for (int jj = kk >> 1; jj > 0; jj >>= 1){
            int i = tid, ixj = tid ^ jj;
            if (ixj > i){
                u64 a = s_key[i], c2 = s_key[ixj];
                bool up = ((i & kk) == 0);
                if (up ? (a < c2) : (a > c2)){ s_key[i] = c2; s_key[ixj] = a; }
            }
            __syncthreads();
        }
    }
    if (tid < KTOP){
        u64 key = s_key[tid];
        unsigned flat = ~(unsigned)key;
        int cls = flat / 100, kk2 = flat - cls*100;
        g_fscore[b*KTOP + tid] = __uint_as_float((unsigned)(key >> 32));
        g_fcls  [b*KTOP + tid] = cls;
        g_find  [b*KTOP + tid] = g_inds[(b*NMAPS + cls)*KTOP + kk2];
    }
}

// =====================================================================
// Kernel 3: 160 CTAs. jobs 0-8 = joint matching; job 9 = scalar gathers
// =====================================================================
__global__ __launch_bounds__(128)
void decode_kernel(const float* __restrict__ wh,  const float* __restrict__ hps,
                   const float* __restrict__ dim, const float* __restrict__ rot,
                   const float* __restrict__ prob,const float* __restrict__ reg,
                   const float* __restrict__ hp_offset, float* __restrict__ out){
    int job = blockIdx.x;
    int b   = blockIdx.y;
    int tid = threadIdx.x;

    if (job == 9){
        if (tid < KTOP){
            int k = tid;
            int ind = g_find[b*KTOP + k];
            float x0 = (float)(ind % WW);
            float y0 = (float)(ind / WW);
            float rx = reg[((size_t)b*2 + 0)*HWSZ + ind];
            float ry = reg[((size_t)b*2 + 1)*HWSZ + ind];
            float xs = x0 + rx, ys = y0 + ry;
            float w0 = wh[((size_t)b*2 + 0)*HWSZ + ind];
            float w1 = wh[((size_t)b*2 + 1)*HWSZ + ind];
            float* det = out + ((size_t)b*KTOP + k)*45;
            det[0] = (xs - w0*0.5f)*4.0f;
            det[1] = (ys - w1*0.5f)*4.0f;
            det[2] = (xs + w0*0.5f)*4.0f;
            det[3] = (ys + w1*0.5f)*4.0f;
            det[4] = g_fscore[b*KTOP + k];
            det[23] = dim[((size_t)b*3 + 0)*HWSZ + ind];
            det[24] = dim[((size_t)b*3 + 1)*HWSZ + ind];
            det[25] = dim[((size_t)b*3 + 2)*HWSZ + ind];
            #pragma unroll
            for (int c = 0; c < 8; c++)
                det[35 + c] = rot[((size_t)b*8 + c)*HWSZ + ind];
            det[43] = prob[(size_t)b*HWSZ + ind];
            det[44] = (float)g_fcls[b*KTOP + k];
        }
        return;
    }

    int j = job;
    __shared__ float hmx[100], hmy[100], hmsc[100];
    __shared__ float bl[100], bt[100], br[100], bbm[100];
    __shared__ float kx[100], ky[100];

    if (tid < KTOP){
        int k = tid;
        int base = (b*NMAPS + 3 + j)*KTOP + k;
        int ind  = g_inds[base];
        float sc = g_scores[base];
        int ind2 = g_find[b*KTOP + k];
        float ox = hp_offset[((size_t)b*2 + 0)*HWSZ + ind];
        float oy = hp_offset[((size_t)b*2 + 1)*HWSZ + ind];
        float rx = reg[((size_t)b*2 + 0)*HWSZ + ind2];
        float ry = reg[((size_t)b*2 + 1)*HWSZ + ind2];
        float w0 = wh[((size_t)b*2 + 0)*HWSZ + ind2];
        float w1 = wh[((size_t)b*2 + 1)*HWSZ + ind2];
        float hx0 = hps[((size_t)b*18 + 2*j    )*HWSZ + ind2];
        float hy0 = hps[((size_t)b*18 + 2*j + 1)*HWSZ + ind2];

        float xq = (float)(ind % WW) + ox;
        float yq = (float)(ind / WW) + oy;
        bool valid = sc > THRESH;
        hmsc[k] = valid ? sc : -1.0f;
        hmx [k] = valid ? xq : -10000.0f;
        hmy [k] = valid ? yq : -10000.0f;

        float x0 = (float)(ind2 % WW);
        float y0 = (float)(ind2 / WW);
        float xs = x0 + rx, ys = y0 + ry;
        bl[k] = xs - w0*0.5f; bt[k]  = ys - w1*0.5f;
        br[k] = xs + w0*0.5f; bbm[k] = ys + w1*0.5f;
        kx[k] = hx0 + x0;
        ky[k] = hy0 + y0;
    }
    __syncthreads();

    if (tid < KTOP){
        int k = tid;
        float px = kx[k], py = ky[k];
        float best = FLT_MAX; int bm = 0;
        #pragma unroll 4
        for (int mm = 0; mm < 100; mm++){
            float dx = px - hmx[mm];
            float dy = py - hmy[mm];
            float d  = sqrtf(dx*dx + dy*dy);
            if (d < best){ best = d; bm = mm; }
        }
        float hs = hmsc[bm], hx = hmx[bm], hy = hmy[bm];
        float l = bl[k], tt = bt[k], r = br[k], bo = bbm[k];
        bool invalid = (hx < l) || (hx > r) || (hy < tt) || (hy > bo) ||
                       (hs < THRESH) ||
                       (best > fmaxf(bo - tt, r - l)*0.3f);
        float fx = invalid ? px : hx;
        float fy = invalid ? py : hy;
        float* det = out + ((size_t)b*KTOP + k)*45;
        det[5 + 2*j] = fx*4.0f;
        det[6 + 2*j] = fy*4.0f;
        det[26 + j]  = hs;
    }
}

// =====================================================================
extern "C" void kernel_launch(void* const* d_in, const int* in_sizes, int n_in,
                              void* d_out, int out_size){
    const float* hm        = (const float*)d_in[0];
    const float* wh        = (const float*)d_in[1];
    const float* hps       = (const float*)d_in[2];
    const float* dim       = (const float*)d_in[3];
    const float* rot       = (const float*)d_in[4];
    const float* prob      = (const float*)d_in[5];
    const float* reg       = (const float*)d_in[6];
    const float* hm_hp     = (const float*)d_in[7];
    const float* hp_offset = (const float*)d_in[8];
    float* out = (float*)d_out;

    const int SMEM1 = 45056 + 32768 + 4096 + 1024 + 128;   // 83072 B
    cudaFuncSetAttribute(topk_map_kernel,
                         cudaFuncAttributeMaxDynamicSharedMemorySize, SMEM1);

    topk_map_kernel<<<BATCH*NMAPS, T1, SMEM1>>>(hm, hm_hp);
    merge_batch_kernel<<<BATCH, 512>>>();
    decode_kernel<<<dim3(10, BATCH), 128>>>(wh, hps, dim, rot, prob, reg, hp_offset, out);
}